// round 15
// baseline (speedup 1.0000x reference)
#include <cuda_runtime.h>
#include <math.h>
#include <stdint.h>

#define LAG   8192
#define KTOK  4
#define DIM   1024
#define HEADS 16
#define DH    64
#define HID   5
#define NCLS  2
#define MROWS (LAG * KTOK)
#define NELEM (MROWS * DIM)

__device__ float g_buf0[NELEM];
__device__ float g_buf1[NELEM];
__device__ float g_buf2[NELEM];
__device__ float g_buf3[NELEM];
__device__ float g_buf4[NELEM];
__device__ float g_buf5[NELEM];
__device__ float g_buf6[NELEM];           // rounded copy of x
__device__ float g_wr[7 * DIM * DIM];     // rounded Rq1,Rk1,Rv1,Ro1,R1,R2,Rq2
__device__ float g_tk2[DIM * DIM];
__device__ float g_m[DIM * DIM];          // M = Wq2 @ Wk2^T (rounded)
__device__ float g_attsc[DIM];
__device__ float g_attv[DIM];
__device__ float g_w1[DIM];
__device__ float g_u[DIM];
__device__ float g_lstm_in[LAG * 9];
__device__ float g_gx[LAG * 20];
__device__ float g_hs[LAG * HID];

__device__ __forceinline__ uint32_t smem_u32(const void* p) {
    return (uint32_t)__cvta_generic_to_shared(p);
}
__device__ __forceinline__ float rnd_tf32(float x) {
    uint32_t r; asm("cvt.rna.tf32.f32 %0, %1;" : "=r"(r) : "f"(x));
    return __uint_as_float(r);
}
__device__ __forceinline__ void cpa16(uint32_t dst, const void* src) {
    asm volatile("cp.async.cg.shared.global [%0], [%1], 16;" :: "r"(dst), "l"(src));
}
__device__ __forceinline__ float ftanh(float x) {
    float y; asm("tanh.approx.f32 %0, %1;" : "=f"(y) : "f"(x)); return y;
}
__device__ __forceinline__ void mma_t(float* d, const uint32_t* a, const uint32_t* b) {
    asm volatile(
        "mma.sync.aligned.m16n8k8.row.col.f32.tf32.tf32.f32 "
        "{%0,%1,%2,%3}, {%4,%5,%6,%7}, {%8,%9}, {%0,%1,%2,%3};"
        : "+f"(d[0]), "+f"(d[1]), "+f"(d[2]), "+f"(d[3])
        : "r"(a[0]), "r"(a[1]), "r"(a[2]), "r"(a[3]), "r"(b[0]), "r"(b[1]));
}

// ------- tf32 mma.sync GEMM: C[M,1024] = A @ W -------
// BM=128, BN=256, BK=32, NST=4 (proven pipeline); NOW 512 threads =
// 16 warps in 4(M) x 4(N), warp tile 32x64 -> 4 warps/SMSP for latency hiding.
#define BM 128
#define BN 256
#define BK 32
#define KITER 32
#define NST 4
#define AST 36
#define BST 260
#define A_STG (BM * AST)
#define B_STG (BK * BST)
#define GEMM_SMEM ((NST * (A_STG + B_STG)) * 4)

__device__ __forceinline__ void g_load(const float* __restrict__ A,
                                       const float* __restrict__ W,
                                       int bm, int kt, int bn,
                                       float* as, float* bs, int tid) {
    float* ab = as + (kt & 3) * A_STG;
    float* bb = bs + (kt & 3) * B_STG;
    int k0 = kt * BK;
    #pragma unroll
    for (int c = tid; c < 1024; c += 512) {
        int m = c >> 3, kq = c & 7;
        cpa16(smem_u32(ab + m * AST + kq * 4),
              A + (size_t)(bm + m) * 1024 + k0 + kq * 4);
    }
    #pragma unroll
    for (int c = tid; c < 2048; c += 512) {
        int k = c >> 6, nq = c & 63;
        cpa16(smem_u32(bb + k * BST + nq * 4),
              W + (size_t)(k0 + k) * 1024 + bn + nq * 4);
    }
    asm volatile("cp.async.commit_group;" ::: "memory");
}

__device__ __forceinline__ void frag_load(const float* ab, const float* bb,
                                          int wm, int wn, int g, int t, int ks,
                                          uint32_t af[2][4], uint32_t bf[8][2]) {
    #pragma unroll
    for (int mi = 0; mi < 2; mi++) {
        const uint32_t* ap = (const uint32_t*)(ab + (wm + mi * 16 + g) * AST + ks * 8 + t);
        af[mi][0] = ap[0];
        af[mi][1] = ap[8 * AST];
        af[mi][2] = ap[4];
        af[mi][3] = ap[8 * AST + 4];
    }
    #pragma unroll
    for (int ni = 0; ni < 8; ni++) {
        const uint32_t* bp = (const uint32_t*)(bb + (ks * 8 + t) * BST + wn + ni * 8 + g);
        bf[ni][0] = bp[0];
        bf[ni][1] = bp[4 * BST];
    }
}

// MODE 0: plain; 1: +bias+relu+rnd; 2: +bias+rnd; 3: +rnd
template<int MODE>
__global__ void __launch_bounds__(512, 1)
tgemm_kernel(const float* __restrict__ A, const float* __restrict__ W,
             const float* __restrict__ bias, float* __restrict__ C) {
    extern __shared__ float sb[];
    float* as = sb;
    float* bs = sb + NST * A_STG;

    int tid = threadIdx.x;
    int wid = tid >> 5, lane = tid & 31;
    int g = lane >> 2, t = lane & 3;
    int bm = blockIdx.y * BM, bn = blockIdx.x * BN;
    int wm = (wid >> 2) * 32;     // 4 warp groups in M, 32 rows each
    int wn = (wid & 3) * 64;      // 4 warp groups in N, 64 cols each

    float acc[2][8][4];
    #pragma unroll
    for (int i = 0; i < 2; i++)
        #pragma unroll
        for (int j = 0; j < 8; j++)
            #pragma unroll
            for (int r = 0; r < 4; r++) acc[i][j][r] = 0.f;

    g_load(A, W, bm, 0, bn, as, bs, tid);
    g_load(A, W, bm, 1, bn, as, bs, tid);

    uint32_t af[2][2][4], bf[2][8][2];

    for (int kt = 0; kt < KITER; kt++) {
        if (kt + 2 < KITER) {
            g_load(A, W, bm, kt + 2, bn, as, bs, tid);
            asm volatile("cp.async.wait_group 2;" ::: "memory");
        } else if (kt == KITER - 2) {
            asm volatile("cp.async.wait_group 1;" ::: "memory");
        } else {
            asm volatile("cp.async.wait_group 0;" ::: "memory");
        }
        __syncthreads();

        const float* ab = as + (kt & 3) * A_STG;
        const float* bb = bs + (kt & 3) * B_STG;

        frag_load(ab, bb, wm, wn, g, t, 0, af[0], bf[0]);
        #pragma unroll
        for (int ks = 0; ks < 4; ks++) {
            int cur = ks & 1;
            if (ks < 3)
                frag_load(ab, bb, wm, wn, g, t, ks + 1, af[cur ^ 1], bf[cur ^ 1]);
            #pragma unroll
            for (int mi = 0; mi < 2; mi++)
                #pragma unroll
                for (int ni = 0; ni < 8; ni++)
                    mma_t(acc[mi][ni], af[cur][mi], bf[cur][ni]);
        }
    }

    #pragma unroll
    for (int mi = 0; mi < 2; mi++) {
        #pragma unroll
        for (int ni = 0; ni < 8; ni++) {
            int row = bm + wm + mi * 16 + g;
            int col = bn + wn + ni * 8 + 2 * t;
            float2 v0 = make_float2(acc[mi][ni][0], acc[mi][ni][1]);
            float2 v1 = make_float2(acc[mi][ni][2], acc[mi][ni][3]);
            if (MODE == 1 || MODE == 2) {
                float b0 = bias[col], b1 = bias[col + 1];
                v0.x += b0; v0.y += b1; v1.x += b0; v1.y += b1;
                if (MODE == 1) {
                    v0.x = fmaxf(v0.x, 0.f); v0.y = fmaxf(v0.y, 0.f);
                    v1.x = fmaxf(v1.x, 0.f); v1.y = fmaxf(v1.y, 0.f);
                }
            }
            if (MODE != 0) {
                v0.x = rnd_tf32(v0.x); v0.y = rnd_tf32(v0.y);
                v1.x = rnd_tf32(v1.x); v1.y = rnd_tf32(v1.y);
            }
            *(float2*)&C[(size_t)row * 1024 + col] = v0;
            *(float2*)&C[(size_t)(row + 8) * 1024 + col] = v1;
        }
    }
}

// round 7 matrices: Rq1, Rk1, Rv1, Ro1, R1, R2, Rq2
__global__ void wprep_kernel(const float* __restrict__ w0, const float* __restrict__ w1,
                             const float* __restrict__ w2, const float* __restrict__ w3,
                             const float* __restrict__ w4, const float* __restrict__ w5,
                             const float* __restrict__ w6,
                             float* __restrict__ dst) {
    const float* srcs[7] = {w0, w1, w2, w3, w4, w5, w6};
    int wsel = blockIdx.y;
    const float4* s = (const float4*)srcs[wsel];
    float4* d = (float4*)(dst + (size_t)wsel * DIM * DIM);
    int n4 = DIM * DIM / 4;
    for (int i = blockIdx.x * blockDim.x + threadIdx.x; i < n4; i += gridDim.x * blockDim.x) {
        float4 v = s[i];
        v.x = rnd_tf32(v.x); v.y = rnd_tf32(v.y);
        v.z = rnd_tf32(v.z); v.w = rnd_tf32(v.w);
        d[i] = v;
    }
}

__global__ void transpose_kernel(const float* __restrict__ in, float* __restrict__ out) {
    __shared__ float t[32][33];
    int bx = blockIdx.x * 32, by = blockIdx.y * 32;
    #pragma unroll
    for (int j = 0; j < 32; j += 8)
        t[threadIdx.y + j][threadIdx.x] = in[(size_t)(by + threadIdx.y + j) * DIM + bx + threadIdx.x];
    __syncthreads();
    #pragma unroll
    for (int j = 0; j < 32; j += 8)
        out[(size_t)(bx + threadIdx.y + j) * DIM + by + threadIdx.x] =
            rnd_tf32(t[threadIdx.x][threadIdx.y + j]);
}

__global__ void matvec_kernel(const float* __restrict__ W, const float* __restrict__ v,
                              float* __restrict__ out) {
    int row = blockIdx.x;
    int t = threadIdx.x;  // 128
    __shared__ float red[4];
    const float4* wp = (const float4*)(W + (size_t)row * DIM);
    const float4* vp = (const float4*)v;
    float s = 0.f;
    for (int j = t; j < 256; j += 128) {
        float4 a = wp[j], b = vp[j];
        s = fmaf(a.x, b.x, s); s = fmaf(a.y, b.y, s);
        s = fmaf(a.z, b.z, s); s = fmaf(a.w, b.w, s);
    }
    int lane = t & 31, w = t >> 5;
    #pragma unroll
    for (int off = 16; off; off >>= 1) s += __shfl_xor_sync(~0u, s, off);
    if (lane == 0) red[w] = s;
    __syncthreads();
    if (t == 0) out[row] = red[0] + red[1] + red[2] + red[3];
}

__global__ void add_kernel(const float* __restrict__ a, const float* __restrict__ b,
                           float* __restrict__ cf, float* __restrict__ cr, int n4) {
    int i = blockIdx.x * blockDim.x + threadIdx.x;
    int stride = gridDim.x * blockDim.x;
    const float4* a4 = (const float4*)a;
    const float4* b4 = (const float4*)b;
    float4* c4 = (float4*)cf;
    float4* r4 = (float4*)cr;
    for (; i < n4; i += stride) {
        float4 x = a4[i], y = b4[i];
        x.x += y.x; x.y += y.y; x.z += y.z; x.w += y.w;
        c4[i] = x;
        float4 r;
        r.x = rnd_tf32(x.x); r.y = rnd_tf32(x.y);
        r.z = rnd_tf32(x.z); r.w = rnd_tf32(x.w);
        r4[i] = r;
    }
}

__global__ void attn1_kernel(const float* __restrict__ q, const float* __restrict__ k,
                             const float* __restrict__ v, float* __restrict__ o) {
    int l = blockIdx.x;
    int t = threadIdx.x;  // 256
    __shared__ float a_s[HEADS][KTOK][KTOK];
    int h = t >> 4, qt = (t >> 2) & 3, kt = t & 3;
    const float4* qp = (const float4*)(q + (size_t)(l * 4 + qt) * DIM + h * DH);
    const float4* kp = (const float4*)(k + (size_t)(l * 4 + kt) * DIM + h * DH);
    float s = 0.f;
    #pragma unroll
    for (int j = 0; j < 16; j++) {
        float4 a = qp[j], b = kp[j];
        s = fmaf(a.x, b.x, s); s = fmaf(a.y, b.y, s);
        s = fmaf(a.z, b.z, s); s = fmaf(a.w, b.w, s);
    }
    s *= 0.125f;
    float m = fmaxf(s, __shfl_xor_sync(~0u, s, 1));
    m = fmaxf(m, __shfl_xor_sync(~0u, m, 2));
    float e = expf(s - m);
    float se = e + __shfl_xor_sync(~0u, e, 1);
    se += __shfl_xor_sync(~0u, se, 2);
    a_s[h][qt][kt] = e / se;
    __syncthreads();
    #pragma unroll
    for (int it = 0; it < 16; it++) {
        int idx = it * 256 + t;
        int qq = idx >> 10, d = idx & 1023, hh = d >> 6;
        float acc = 0.f;
        #pragma unroll
        for (int kk = 0; kk < 4; kk++)
            acc = fmaf(a_s[hh][qq][kk], v[(size_t)(l * 4 + kk) * DIM + d], acc);
        o[(size_t)(l * 4 + qq) * DIM + d] = rnd_tf32(acc);
    }
}

__global__ void ln_kernel(const float* __restrict__ inter, const float* __restrict__ x,
                          const float* __restrict__ g, const float* __restrict__ b,
                          float* __restrict__ y) {
    int row = blockIdx.x;
    int t = threadIdx.x;  // 256
    __shared__ float red1[32], red2[32], bc[2];
    const float4* pi = (const float4*)(inter + (size_t)row * DIM);
    const float4* px = (const float4*)(x + (size_t)row * DIM);
    float4 vi = pi[t], vx = px[t];
    float v0 = vi.x + vx.x, v1 = vi.y + vx.y, v2 = vi.z + vx.z, v3 = vi.w + vx.w;
    float sum = v0 + v1 + v2 + v3;
    float sq = v0 * v0 + v1 * v1 + v2 * v2 + v3 * v3;
    int lane = t & 31, w = t >> 5;
    #pragma unroll
    for (int off = 16; off; off >>= 1) {
        sum += __shfl_xor_sync(~0u, sum, off);
        sq  += __shfl_xor_sync(~0u, sq, off);
    }
    if (lane == 0) { red1[w] = sum; red2[w] = sq; }
    __syncthreads();
    if (w == 0) {
        float r1 = (lane < 8) ? red1[lane] : 0.f;
        float r2 = (lane < 8) ? red2[lane] : 0.f;
        #pragma unroll
        for (int off = 4; off; off >>= 1) {
            r1 += __shfl_xor_sync(~0u, r1, off);
            r2 += __shfl_xor_sync(~0u, r2, off);
        }
        if (lane == 0) { bc[0] = r1; bc[1] = r2; }
    }
    __syncthreads();
    float mean = bc[0] * (1.0f / DIM);
    float var = bc[1] * (1.0f / DIM) - mean * mean;
    float inv = rsqrtf(var + 1e-5f);
    int c = t * 4;
    float4 out;
    out.x = rnd_tf32((v0 - mean) * inv * g[c + 0] + b[c + 0]);
    out.y = rnd_tf32((v1 - mean) * inv * g[c + 1] + b[c + 1]);
    out.z = rnd_tf32((v2 - mean) * inv * g[c + 2] + b[c + 2]);
    out.w = rnd_tf32((v3 - mean) * inv * g[c + 3] + b[c + 3]);
    *(float4*)(y + (size_t)row * DIM + c) = out;
}

// fused attn2 + pooling
__global__ void attn2pool_kernel(const float* __restrict__ T, const float* __restrict__ ffn,
                                 const float* __restrict__ u, const float* __restrict__ prices,
                                 float* __restrict__ lstm_in) {
    int l = blockIdx.x;
    int t = threadIdx.x;  // 512
    int w = t >> 5, lane = t & 31;
    __shared__ float s_s[KTOK][KTOK], fk_s[KTOK];
    if (w < 16) {
        int qt = w >> 2, kt = w & 3;
        const float4* qp = (const float4*)(T + (size_t)(l * 4 + qt) * DIM);
        const float4* kp = (const float4*)(ffn + (size_t)(l * 4 + kt) * DIM);
        const float4* up = (const float4*)u;
        float s = 0.f, s2 = 0.f;
        for (int j = lane; j < 256; j += 32) {
            float4 a = qp[j], b = kp[j];
            s = fmaf(a.x, b.x, s); s = fmaf(a.y, b.y, s);
            s = fmaf(a.z, b.z, s); s = fmaf(a.w, b.w, s);
            if (qt == 0) {
                float4 uu = up[j];
                s2 = fmaf(b.x, uu.x, s2); s2 = fmaf(b.y, uu.y, s2);
                s2 = fmaf(b.z, uu.z, s2); s2 = fmaf(b.w, uu.w, s2);
            }
        }
        #pragma unroll
        for (int off = 16; off; off >>= 1) {
            s  += __shfl_xor_sync(~0u, s, off);
            s2 += __shfl_xor_sync(~0u, s2, off);
        }
        if (lane == 0) {
            s_s[qt][kt] = s * (1.0f / 32.0f);
            if (qt == 0) fk_s[kt] = s2;
        }
    }
    __syncthreads();
    if (t < 4) {
        float m = -1e30f;
        #pragma unroll
        for (int kk = 0; kk < 4; kk++) m = fmaxf(m, s_s[t][kk]);
        float sum = 0.f, acc = 0.f;
        #pragma unroll
        for (int kk = 0; kk < 4; kk++) {
            float e = expf(s_s[t][kk] - m);
            sum += e;
            acc = fmaf(e, fk_s[kk], acc);
        }
        lstm_in[l * 9 + t] = acc / sum;
    }
    if (t >= 8 && t < 13) lstm_in[l * 9 + 4 + (t - 8)] = prices[l * 5 + (t - 8)];
}

// attvec three-stage
__global__ void attvec_zero_kernel(float* __restrict__ sc) {
    sc[threadIdx.x] = 0.f;
}

__global__ void attvec_score_kernel(const float* __restrict__ w_u, const float* __restrict__ w_m,
                                    float* __restrict__ sc) {
    __shared__ float tsm[128];
    int t = threadIdx.x;                       // 128
    int col = (blockIdx.x & 7) * 128 + t;
    int i0 = (blockIdx.x >> 3) * 128;
    tsm[t] = tanhf(w_m[i0 + t]);
    __syncthreads();
    float u = 0.f;
    #pragma unroll 4
    for (int i = 0; i < 128; i++)
        u = fmaf(w_u[(size_t)(i0 + i) * DIM + col], tsm[i], u);
    atomicAdd(&sc[col], u);
}

__global__ void attvec_softmax_kernel(const float* __restrict__ sc, float* __restrict__ att) {
    __shared__ float red[32], bc[1];
    int t = threadIdx.x;  // 1024
    float u = sc[t];
    int lane = t & 31, w = t >> 5;
    float m = u;
    #pragma unroll
    for (int off = 16; off; off >>= 1) m = fmaxf(m, __shfl_xor_sync(~0u, m, off));
    if (lane == 0) red[w] = m;
    __syncthreads();
    if (w == 0) {
        float r = red[lane];
        #pragma unroll
        for (int off = 16; off; off >>= 1) r = fmaxf(r, __shfl_xor_sync(~0u, r, off));
        if (lane == 0) bc[0] = r;
    }
    __syncthreads();
    float gmax = bc[0];
    __syncthreads();
    float e = expf(u - gmax);
    float s = e;
    #pragma unroll
    for (int off = 16; off; off >>= 1) s += __shfl_xor_sync(~0u, s, off);
    if (lane == 0) red[w] = s;
    __syncthreads();
    if (w == 0) {
        float r = red[lane];
        #pragma unroll
        for (int off = 16; off; off >>= 1) r += __shfl_xor_sync(~0u, r, off);
        if (lane == 0) bc[0] = r;
    }
    __syncthreads();
    att[t] = e / bc[0];
}

__global__ void gx_kernel(const float* __restrict__ lstm_in, const float* __restrict__ Wih,
                          const float* __restrict__ bih, const float* __restrict__ bhh,
                          float* __restrict__ gx) {
    int idx = blockIdx.x * blockDim.x + threadIdx.x;
    if (idx >= LAG * 20) return;
    int l = idx / 20, j = idx % 20;
    float s = bih[j] + bhh[j];
    const float* xi = lstm_in + l * 9;
    const float* wr = Wih + j * 9;
    #pragma unroll
    for (int i = 0; i < 9; i++) s = fmaf(wr[i], xi[i], s);
    gx[idx] = s;
}

__global__ void lstm_kernel(const float* __restrict__ gx, const float* __restrict__ Whh,
                            float* __restrict__ hs) {
    int j = threadIdx.x;
    float w0 = 0.f, w1 = 0.f, w2 = 0.f, w3 = 0.f, w4 = 0.f;
    if (j < 20) {
        w0 = Whh[j * 5 + 0]; w1 = Whh[j * 5 + 1]; w2 = Whh[j * 5 + 2];
        w3 = Whh[j * 5 + 3]; w4 = Whh[j * 5 + 4];
    }
    float h0 = 0.f, h1 = 0.f, h2 = 0.f, h3 = 0.f, h4 = 0.f, c = 0.f;
    bool isg = (j >= 10 && j < 15);
    float pre = isg ? 1.0f : 0.5f;
    float pm  = isg ? 1.0f : 0.5f;
    float pb  = isg ? 0.0f : 0.5f;
    float gA = (j < 20) ? gx[j] : 0.f;
    float gB = (j < 20) ? gx[20 + j] : 0.f;
    for (int l = 0; l < LAG; l++) {
        float gN = 0.f;
        if (l + 2 < LAG && j < 20) gN = gx[(l + 2) * 20 + j];
        float g = gA;
        g = fmaf(w0, h0, g); g = fmaf(w1, h1, g); g = fmaf(w2, h2, g);
        g = fmaf(w3, h3, g); g = fmaf(w4, h4, g);
        float a = fmaf(pm, ftanh(pre * g), pb);
        float f_ = __shfl_sync(~0u, a, (j + 5) & 31);
        float g_ = __shfl_sync(~0u, a, (j + 10) & 31);
        float o_ = __shfl_sync(~0u, a, (j + 15) & 31);
        float hv = 0.f;
        if (j < 5) c = fmaf(f_, c, a * g_);
        float tc = ftanh(c);
        if (j < 5) { hv = o_ * tc; hs[l * HID + j] = hv; }
        h0 = __shfl_sync(~0u, hv, 0); h1 = __shfl_sync(~0u, hv, 1);
        h2 = __shfl_sync(~0u, hv, 2); h3 = __shfl_sync(~0u, hv, 3);
        h4 = __shfl_sync(~0u, hv, 4);
        gA = gB; gB = gN;
    }
}

__global__ void head_kernel(const float* __restrict__ lstm_in, const float* __restrict__ hs,
                            const float* __restrict__ Wt, const float* __restrict__ bt,
                            const float* __restrict__ Wa, const float* __restrict__ ba,
                            float* __restrict__ out) {
    int l = blockIdx.x * blockDim.x + threadIdx.x;
    if (l >= LAG) return;
    float f[14];
    #pragma unroll
    for (int i = 0; i < 9; i++) f[i] = lstm_in[l * 9 + i];
    #pragma unroll
    for (int i = 0; i < 5; i++) f[9 + i] = hs[l * HID + i];
    #pragma unroll
    for (int cidx = 0; cidx < NCLS; cidx++) {
        float s = bt[cidx];
        #pragma unroll
        for (int i = 0; i < 14; i++) s = fmaf(f[i], Wt[i * NCLS + cidx], s);
        out[(size_t)l * NCLS + cidx] = s;
    }
    #pragma unroll
    for (int cidx = 0; cidx < NCLS; cidx++) {
        float s = ba[cidx];
        #pragma unroll
        for (int i = 0; i < 14; i++) s = fmaf(f[i], Wa[i * NCLS + cidx], s);
        out[(size_t)LAG * NCLS + (size_t)l * NCLS + cidx] = s;
    }
}

extern "C" void kernel_launch(void* const* d_in, const int* in_sizes, int n_in,
                              void* d_out, int out_size) {
    const float* text      = (const float*)d_in[0];
    const float* prices    = (const float*)d_in[1];
    const float* pos_embed = (const float*)d_in[2];
    const float* Wq1 = (const float*)d_in[3];
    const float* Wk1 = (const float*)d_in[4];
    const float* Wv1 = (const float*)d_in[5];
    const float* Wo1 = (const float*)d_in[6];
    const float* ln_g = (const float*)d_in[7];
    const float* ln_b = (const float*)d_in[8];
    const float* W1 = (const float*)d_in[9];
    const float* b1 = (const float*)d_in[10];
    const float* W2 = (const float*)d_in[11];
    const float* b2 = (const float*)d_in[12];
    const float* Wq2 = (const float*)d_in[13];
    const float* Wk2 = (const float*)d_in[14];
    const float* Wv2 = (const float*)d_in[15];
    const float* Wo2 = (const float*)d_in[16];
    const float* w_u = (const float*)d_in[17];
    const float* w_m = (const float*)d_in[18];
    const float* Wih = (const float*)d_in[19];
    const float* Whh = (const float*)d_in[20];
    const float* bih = (const float*)d_in[21];
    const float* bhh = (const float*)d_in[22];
    const float* Wt = (const float*)d_in[23];
    const float* bt = (const float*)d_in[24];
    const float* Wa = (const float*)d_in[25];
    const float* ba = (const float*)d_in[26];
    float* out = (float*)d_out;

    float *B0, *B1, *B2, *B3, *B4, *B5, *B6, *WR, *TK2, *MB, *ATSC;
    float *attv, *w1v, *uv, *lstm_in, *gx, *hs;
    cudaGetSymbolAddress((void**)&B0, g_buf0);
    cudaGetSymbolAddress((void**)&B1, g_buf1);
    cudaGetSymbolAddress((void**)&B2, g_buf2);
    cudaGetSymbolAddress((void**)&B3, g_buf3);
    cudaGetSymbolAddress((void**)&B4, g_buf4);
    cudaGetSymbolAddress((void**)&B5, g_buf5);
    cudaGetSymbolAddress((void**)&B6, g_buf6);
    cudaGetSymbolAddress((void**)&WR, g_wr);
    cudaGetSymbolAddress((void**)&TK2, g_tk2);
    cudaGetSymbolAddress((void**)&MB, g_m);
    cudaGetSymbolAddress((void**)&ATSC, g_attsc);
    cudaGetSymbolAddress((void**)&attv, g_attv);
    cudaGetSymbolAddress((void**)&w1v, g_w1);
    cudaGetSymbolAddress((void**)&uv, g_u);
    cudaGetSymbolAddress((void**)&lstm_in, g_lstm_in);
    cudaGetSymbolAddress((void**)&gx, g_gx);
    cudaGetSymbolAddress((void**)&hs, g_hs);

    cudaFuncSetAttribute(tgemm_kernel<0>, cudaFuncAttributeMaxDynamicSharedMemorySize, GEMM_SMEM);
    cudaFuncSetAttribute(tgemm_kernel<1>, cudaFuncAttributeMaxDynamicSharedMemorySize, GEMM_SMEM);
    cudaFuncSetAttribute(tgemm_kernel<2>, cudaFuncAttributeMaxDynamicSharedMemorySize, GEMM_SMEM);
    cudaFuncSetAttribute(tgemm_kernel<3>, cudaFuncAttributeMaxDynamicSharedMemorySize, GEMM_SMEM);

    const size_t WSZ = (size_t)DIM * DIM;
    float* Rq1 = WR + 0 * WSZ; float* Rk1 = WR + 1 * WSZ;
    float* Rv1 = WR + 2 * WSZ; float* Ro1 = WR + 3 * WSZ;
    float* R1  = WR + 4 * WSZ; float* R2  = WR + 5 * WSZ;
    float* Rq2 = WR + 6 * WSZ;

    dim3 ggrid(DIM / BN, MROWS / BM);    // (4, 256)
    dim3 mgrid(DIM / BN, DIM / BM);      // (4, 8)
    dim3 wgrid(128, 7);
    dim3 tgrid(32, 32), tblk(32, 8);

    // prep
    wprep_kernel<<<wgrid, 256>>>(Wq1, Wk1, Wv1, Wo1, W1, W2, Wq2, WR);
    transpose_kernel<<<tgrid, tblk>>>(Wk2, TK2);
    attvec_zero_kernel<<<1, 1024>>>(ATSC);
    attvec_score_kernel<<<64, 128>>>(w_u, w_m, ATSC);
    attvec_softmax_kernel<<<1, 1024>>>(ATSC, attv);
    matvec_kernel<<<DIM, 128>>>(Wo2, attv, w1v);
    matvec_kernel<<<DIM, 128>>>(Wv2, w1v, uv);
    tgemm_kernel<3><<<mgrid, 512, GEMM_SMEM>>>(Rq2, TK2, nullptr, MB);

    // x = text + pos (B0 full, B6 rounded)
    add_kernel<<<4096, 256>>>(text, pos_embed, B0, B6, NELEM / 4);

    // MHA1
    tgemm_kernel<0><<<ggrid, 512, GEMM_SMEM>>>(B6, Rq1, nullptr, B1);
    tgemm_kernel<0><<<ggrid, 512, GEMM_SMEM>>>(B6, Rk1, nullptr, B2);
    tgemm_kernel<0><<<ggrid, 512, GEMM_SMEM>>>(B6, Rv1, nullptr, B3);
    attn1_kernel<<<LAG, 256>>>(B1, B2, B3, B4);
    tgemm_kernel<0><<<ggrid, 512, GEMM_SMEM>>>(B4, Ro1, nullptr, B5);

    // residual + LN
    ln_kernel<<<MROWS, 256>>>(B5, B0, ln_g, ln_b, B1);

    // FFN (B3 = ffn output, rounded)
    tgemm_kernel<1><<<ggrid, 512, GEMM_SMEM>>>(B1, R1, b1, B2);
    tgemm_kernel<2><<<ggrid, 512, GEMM_SMEM>>>(B2, R2, b2, B3);

    // MHA2 collapsed: T = ffn @ M, then fused attention + pooling
    tgemm_kernel<0><<<ggrid, 512, GEMM_SMEM>>>(B3, MB, nullptr, B0);
    attn2pool_kernel<<<LAG, 512>>>(B0, B3, uv, prices, lstm_in);

    // LSTM + heads
    gx_kernel<<<(LAG * 20 + 255) / 256, 256>>>(lstm_in, Wih, bih, bhh, gx);
    lstm_kernel<<<1, 32>>>(gx, Whh, hs);
    head_kernel<<<(LAG + 255) / 256, 256>>>(lstm_in, hs, Wt, bt, Wa, ba, out);
}

// round 16
// speedup vs baseline: 1.1866x; 1.1866x over previous
#include <cuda_runtime.h>
#include <math.h>
#include <stdint.h>

#define LAG   8192
#define KTOK  4
#define DIM   1024
#define HEADS 16
#define DH    64
#define HID   5
#define NCLS  2
#define MROWS (LAG * KTOK)
#define NELEM (MROWS * DIM)

__device__ float g_buf0[NELEM];
__device__ float g_buf1[NELEM];
__device__ float g_buf2[NELEM];
__device__ float g_buf3[NELEM];
__device__ float g_buf4[NELEM];
__device__ float g_buf5[NELEM];
__device__ float g_buf6[NELEM];           // rounded copy of x
__device__ float g_wr[7 * DIM * DIM];     // rounded Rq1,Rk1,Rv1,Ro1,R1,R2,Rq2
__device__ float g_tk2[DIM * DIM];
__device__ float g_m[DIM * DIM];          // M = Wq2 @ Wk2^T (rounded)
__device__ float g_attsc[DIM];
__device__ float g_attv[DIM];
__device__ float g_w1[DIM];
__device__ float g_u[DIM];
__device__ float g_lstm_in[LAG * 9];
__device__ float g_gx[LAG * 20];
__device__ float g_hs[LAG * HID];

__device__ __forceinline__ uint32_t smem_u32(const void* p) {
    return (uint32_t)__cvta_generic_to_shared(p);
}
__device__ __forceinline__ float rnd_tf32(float x) {
    uint32_t r; asm("cvt.rna.tf32.f32 %0, %1;" : "=r"(r) : "f"(x));
    return __uint_as_float(r);
}
__device__ __forceinline__ void cpa16(uint32_t dst, const void* src) {
    asm volatile("cp.async.cg.shared.global [%0], [%1], 16;" :: "r"(dst), "l"(src));
}
__device__ __forceinline__ float ftanh(float x) {
    float y; asm("tanh.approx.f32 %0, %1;" : "=f"(y) : "f"(x)); return y;
}
__device__ __forceinline__ void mma_t(float* d, const uint32_t* a, const uint32_t* b) {
    asm volatile(
        "mma.sync.aligned.m16n8k8.row.col.f32.tf32.tf32.f32 "
        "{%0,%1,%2,%3}, {%4,%5,%6,%7}, {%8,%9}, {%0,%1,%2,%3};"
        : "+f"(d[0]), "+f"(d[1]), "+f"(d[2]), "+f"(d[3])
        : "r"(a[0]), "r"(a[1]), "r"(a[2]), "r"(a[3]), "r"(b[0]), "r"(b[1]));
}

// ------- tf32 mma.sync GEMM (round-8/14 proven): C[M,1024] = A @ W -------
// BM=128, BN=256, BK=32, NST=4; 256 threads = 8 warps in 2(M) x 4(N), warp tile 64x64.
#define BM 128
#define BN 256
#define BK 32
#define KITER 32
#define NST 4
#define AST 36
#define BST 260
#define A_STG (BM * AST)
#define B_STG (BK * BST)
#define GEMM_SMEM ((NST * (A_STG + B_STG)) * 4)

__device__ __forceinline__ void g_load(const float* __restrict__ A,
                                       const float* __restrict__ W,
                                       int bm, int kt, int bn,
                                       float* as, float* bs, int tid) {
    float* ab = as + (kt & 3) * A_STG;
    float* bb = bs + (kt & 3) * B_STG;
    int k0 = kt * BK;
    #pragma unroll
    for (int c = tid; c < 1024; c += 256) {
        int m = c >> 3, kq = c & 7;
        cpa16(smem_u32(ab + m * AST + kq * 4),
              A + (size_t)(bm + m) * 1024 + k0 + kq * 4);
    }
    #pragma unroll
    for (int c = tid; c < 2048; c += 256) {
        int k = c >> 6, nq = c & 63;
        cpa16(smem_u32(bb + k * BST + nq * 4),
              W + (size_t)(k0 + k) * 1024 + bn + nq * 4);
    }
    asm volatile("cp.async.commit_group;" ::: "memory");
}

__device__ __forceinline__ void frag_load(const float* ab, const float* bb,
                                          int wm, int wn, int g, int t, int ks,
                                          uint32_t af[4][4], uint32_t bf[8][2]) {
    #pragma unroll
    for (int mi = 0; mi < 4; mi++) {
        const uint32_t* ap = (const uint32_t*)(ab + (wm + mi * 16 + g) * AST + ks * 8 + t);
        af[mi][0] = ap[0];
        af[mi][1] = ap[8 * AST];
        af[mi][2] = ap[4];
        af[mi][3] = ap[8 * AST + 4];
    }
    #pragma unroll
    for (int ni = 0; ni < 8; ni++) {
        const uint32_t* bp = (const uint32_t*)(bb + (ks * 8 + t) * BST + wn + ni * 8 + g);
        bf[ni][0] = bp[0];
        bf[ni][1] = bp[4 * BST];
    }
}

// MODE 0: plain; 1: +bias+relu+rnd; 2: +bias+rnd; 3: +rnd
template<int MODE>
__global__ void __launch_bounds__(256, 1)
tgemm_kernel(const float* __restrict__ A, const float* __restrict__ W,
             const float* __restrict__ bias, float* __restrict__ C) {
    extern __shared__ float sb[];
    float* as = sb;
    float* bs = sb + NST * A_STG;

    int tid = threadIdx.x;
    int wid = tid >> 5, lane = tid & 31;
    int g = lane >> 2, t = lane & 3;
    int bm = blockIdx.y * BM, bn = blockIdx.x * BN;
    int wm = (wid >> 2) * 64;
    int wn = (wid & 3) * 64;

    float acc[4][8][4];
    #pragma unroll
    for (int i = 0; i < 4; i++)
        #pragma unroll
        for (int j = 0; j < 8; j++)
            #pragma unroll
            for (int r = 0; r < 4; r++) acc[i][j][r] = 0.f;

    g_load(A, W, bm, 0, bn, as, bs, tid);
    g_load(A, W, bm, 1, bn, as, bs, tid);

    uint32_t af[2][4][4], bf[2][8][2];

    for (int kt = 0; kt < KITER; kt++) {
        if (kt + 2 < KITER) {
            g_load(A, W, bm, kt + 2, bn, as, bs, tid);
            asm volatile("cp.async.wait_group 2;" ::: "memory");
        } else if (kt == KITER - 2) {
            asm volatile("cp.async.wait_group 1;" ::: "memory");
        } else {
            asm volatile("cp.async.wait_group 0;" ::: "memory");
        }
        __syncthreads();

        const float* ab = as + (kt & 3) * A_STG;
        const float* bb = bs + (kt & 3) * B_STG;

        frag_load(ab, bb, wm, wn, g, t, 0, af[0], bf[0]);
        #pragma unroll
        for (int ks = 0; ks < 4; ks++) {
            int cur = ks & 1;
            if (ks < 3)
                frag_load(ab, bb, wm, wn, g, t, ks + 1, af[cur ^ 1], bf[cur ^ 1]);
            #pragma unroll
            for (int mi = 0; mi < 4; mi++)
                #pragma unroll
                for (int ni = 0; ni < 8; ni++)
                    mma_t(acc[mi][ni], af[cur][mi], bf[cur][ni]);
        }
    }

    #pragma unroll
    for (int mi = 0; mi < 4; mi++) {
        #pragma unroll
        for (int ni = 0; ni < 8; ni++) {
            int row = bm + wm + mi * 16 + g;
            int col = bn + wn + ni * 8 + 2 * t;
            float2 v0 = make_float2(acc[mi][ni][0], acc[mi][ni][1]);
            float2 v1 = make_float2(acc[mi][ni][2], acc[mi][ni][3]);
            if (MODE == 1 || MODE == 2) {
                float b0 = bias[col], b1 = bias[col + 1];
                v0.x += b0; v0.y += b1; v1.x += b0; v1.y += b1;
                if (MODE == 1) {
                    v0.x = fmaxf(v0.x, 0.f); v0.y = fmaxf(v0.y, 0.f);
                    v1.x = fmaxf(v1.x, 0.f); v1.y = fmaxf(v1.y, 0.f);
                }
            }
            if (MODE != 0) {
                v0.x = rnd_tf32(v0.x); v0.y = rnd_tf32(v0.y);
                v1.x = rnd_tf32(v1.x); v1.y = rnd_tf32(v1.y);
            }
            *(float2*)&C[(size_t)row * 1024 + col] = v0;
            *(float2*)&C[(size_t)(row + 8) * 1024 + col] = v1;
        }
    }
}

// round 7 matrices: Rq1, Rk1, Rv1, Ro1, R1, R2, Rq2
__global__ void wprep_kernel(const float* __restrict__ w0, const float* __restrict__ w1,
                             const float* __restrict__ w2, const float* __restrict__ w3,
                             const float* __restrict__ w4, const float* __restrict__ w5,
                             const float* __restrict__ w6,
                             float* __restrict__ dst) {
    const float* srcs[7] = {w0, w1, w2, w3, w4, w5, w6};
    int wsel = blockIdx.y;
    const float4* s = (const float4*)srcs[wsel];
    float4* d = (float4*)(dst + (size_t)wsel * DIM * DIM);
    int n4 = DIM * DIM / 4;
    for (int i = blockIdx.x * blockDim.x + threadIdx.x; i < n4; i += gridDim.x * blockDim.x) {
        float4 v = s[i];
        v.x = rnd_tf32(v.x); v.y = rnd_tf32(v.y);
        v.z = rnd_tf32(v.z); v.w = rnd_tf32(v.w);
        d[i] = v;
    }
}

__global__ void transpose_kernel(const float* __restrict__ in, float* __restrict__ out) {
    __shared__ float t[32][33];
    int bx = blockIdx.x * 32, by = blockIdx.y * 32;
    #pragma unroll
    for (int j = 0; j < 32; j += 8)
        t[threadIdx.y + j][threadIdx.x] = in[(size_t)(by + threadIdx.y + j) * DIM + bx + threadIdx.x];
    __syncthreads();
    #pragma unroll
    for (int j = 0; j < 32; j += 8)
        out[(size_t)(bx + threadIdx.y + j) * DIM + by + threadIdx.x] =
            rnd_tf32(t[threadIdx.x][threadIdx.y + j]);
}

__global__ void matvec_kernel(const float* __restrict__ W, const float* __restrict__ v,
                              float* __restrict__ out) {
    int row = blockIdx.x;
    int t = threadIdx.x;  // 128
    __shared__ float red[4];
    const float4* wp = (const float4*)(W + (size_t)row * DIM);
    const float4* vp = (const float4*)v;
    float s = 0.f;
    for (int j = t; j < 256; j += 128) {
        float4 a = wp[j], b = vp[j];
        s = fmaf(a.x, b.x, s); s = fmaf(a.y, b.y, s);
        s = fmaf(a.z, b.z, s); s = fmaf(a.w, b.w, s);
    }
    int lane = t & 31, w = t >> 5;
    #pragma unroll
    for (int off = 16; off; off >>= 1) s += __shfl_xor_sync(~0u, s, off);
    if (lane == 0) red[w] = s;
    __syncthreads();
    if (t == 0) out[row] = red[0] + red[1] + red[2] + red[3];
}

__global__ void add_kernel(const float* __restrict__ a, const float* __restrict__ b,
                           float* __restrict__ cf, float* __restrict__ cr, int n4) {
    int i = blockIdx.x * blockDim.x + threadIdx.x;
    int stride = gridDim.x * blockDim.x;
    const float4* a4 = (const float4*)a;
    const float4* b4 = (const float4*)b;
    float4* c4 = (float4*)cf;
    float4* r4 = (float4*)cr;
    for (; i < n4; i += stride) {
        float4 x = a4[i], y = b4[i];
        x.x += y.x; x.y += y.y; x.z += y.z; x.w += y.w;
        c4[i] = x;
        float4 r;
        r.x = rnd_tf32(x.x); r.y = rnd_tf32(x.y);
        r.z = rnd_tf32(x.z); r.w = rnd_tf32(x.w);
        r4[i] = r;
    }
}

__global__ void attn1_kernel(const float* __restrict__ q, const float* __restrict__ k,
                             const float* __restrict__ v, float* __restrict__ o) {
    int l = blockIdx.x;
    int t = threadIdx.x;  // 256
    __shared__ float a_s[HEADS][KTOK][KTOK];
    int h = t >> 4, qt = (t >> 2) & 3, kt = t & 3;
    const float4* qp = (const float4*)(q + (size_t)(l * 4 + qt) * DIM + h * DH);
    const float4* kp = (const float4*)(k + (size_t)(l * 4 + kt) * DIM + h * DH);
    float s = 0.f;
    #pragma unroll
    for (int j = 0; j < 16; j++) {
        float4 a = qp[j], b = kp[j];
        s = fmaf(a.x, b.x, s); s = fmaf(a.y, b.y, s);
        s = fmaf(a.z, b.z, s); s = fmaf(a.w, b.w, s);
    }
    s *= 0.125f;
    float m = fmaxf(s, __shfl_xor_sync(~0u, s, 1));
    m = fmaxf(m, __shfl_xor_sync(~0u, m, 2));
    float e = expf(s - m);
    float se = e + __shfl_xor_sync(~0u, e, 1);
    se += __shfl_xor_sync(~0u, se, 2);
    a_s[h][qt][kt] = e / se;
    __syncthreads();
    #pragma unroll
    for (int it = 0; it < 16; it++) {
        int idx = it * 256 + t;
        int qq = idx >> 10, d = idx & 1023, hh = d >> 6;
        float acc = 0.f;
        #pragma unroll
        for (int kk = 0; kk < 4; kk++)
            acc = fmaf(a_s[hh][qq][kk], v[(size_t)(l * 4 + kk) * DIM + d], acc);
        o[(size_t)(l * 4 + qq) * DIM + d] = rnd_tf32(acc);
    }
}

__global__ void ln_kernel(const float* __restrict__ inter, const float* __restrict__ x,
                          const float* __restrict__ g, const float* __restrict__ b,
                          float* __restrict__ y) {
    int row = blockIdx.x;
    int t = threadIdx.x;  // 256
    __shared__ float red1[32], red2[32], bc[2];
    const float4* pi = (const float4*)(inter + (size_t)row * DIM);
    const float4* px = (const float4*)(x + (size_t)row * DIM);
    float4 vi = pi[t], vx = px[t];
    float v0 = vi.x + vx.x, v1 = vi.y + vx.y, v2 = vi.z + vx.z, v3 = vi.w + vx.w;
    float sum = v0 + v1 + v2 + v3;
    float sq = v0 * v0 + v1 * v1 + v2 * v2 + v3 * v3;
    int lane = t & 31, w = t >> 5;
    #pragma unroll
    for (int off = 16; off; off >>= 1) {
        sum += __shfl_xor_sync(~0u, sum, off);
        sq  += __shfl_xor_sync(~0u, sq, off);
    }
    if (lane == 0) { red1[w] = sum; red2[w] = sq; }
    __syncthreads();
    if (w == 0) {
        float r1 = (lane < 8) ? red1[lane] : 0.f;
        float r2 = (lane < 8) ? red2[lane] : 0.f;
        #pragma unroll
        for (int off = 4; off; off >>= 1) {
            r1 += __shfl_xor_sync(~0u, r1, off);
            r2 += __shfl_xor_sync(~0u, r2, off);
        }
        if (lane == 0) { bc[0] = r1; bc[1] = r2; }
    }
    __syncthreads();
    float mean = bc[0] * (1.0f / DIM);
    float var = bc[1] * (1.0f / DIM) - mean * mean;
    float inv = rsqrtf(var + 1e-5f);
    int c = t * 4;
    float4 out;
    out.x = rnd_tf32((v0 - mean) * inv * g[c + 0] + b[c + 0]);
    out.y = rnd_tf32((v1 - mean) * inv * g[c + 1] + b[c + 1]);
    out.z = rnd_tf32((v2 - mean) * inv * g[c + 2] + b[c + 2]);
    out.w = rnd_tf32((v3 - mean) * inv * g[c + 3] + b[c + 3]);
    *(float4*)(y + (size_t)row * DIM + c) = out;
}

// fused attn2 + pooling
__global__ void attn2pool_kernel(const float* __restrict__ T, const float* __restrict__ ffn,
                                 const float* __restrict__ u, const float* __restrict__ prices,
                                 float* __restrict__ lstm_in) {
    int l = blockIdx.x;
    int t = threadIdx.x;  // 512
    int w = t >> 5, lane = t & 31;
    __shared__ float s_s[KTOK][KTOK], fk_s[KTOK];
    if (w < 16) {
        int qt = w >> 2, kt = w & 3;
        const float4* qp = (const float4*)(T + (size_t)(l * 4 + qt) * DIM);
        const float4* kp = (const float4*)(ffn + (size_t)(l * 4 + kt) * DIM);
        const float4* up = (const float4*)u;
        float s = 0.f, s2 = 0.f;
        for (int j = lane; j < 256; j += 32) {
            float4 a = qp[j], b = kp[j];
            s = fmaf(a.x, b.x, s); s = fmaf(a.y, b.y, s);
            s = fmaf(a.z, b.z, s); s = fmaf(a.w, b.w, s);
            if (qt == 0) {
                float4 uu = up[j];
                s2 = fmaf(b.x, uu.x, s2); s2 = fmaf(b.y, uu.y, s2);
                s2 = fmaf(b.z, uu.z, s2); s2 = fmaf(b.w, uu.w, s2);
            }
        }
        #pragma unroll
        for (int off = 16; off; off >>= 1) {
            s  += __shfl_xor_sync(~0u, s, off);
            s2 += __shfl_xor_sync(~0u, s2, off);
        }
        if (lane == 0) {
            s_s[qt][kt] = s * (1.0f / 32.0f);
            if (qt == 0) fk_s[kt] = s2;
        }
    }
    __syncthreads();
    if (t < 4) {
        float m = -1e30f;
        #pragma unroll
        for (int kk = 0; kk < 4; kk++) m = fmaxf(m, s_s[t][kk]);
        float sum = 0.f, acc = 0.f;
        #pragma unroll
        for (int kk = 0; kk < 4; kk++) {
            float e = expf(s_s[t][kk] - m);
            sum += e;
            acc = fmaf(e, fk_s[kk], acc);
        }
        lstm_in[l * 9 + t] = acc / sum;
    }
    if (t >= 8 && t < 13) lstm_in[l * 9 + 4 + (t - 8)] = prices[l * 5 + (t - 8)];
}

// attvec three-stage
__global__ void attvec_zero_kernel(float* __restrict__ sc) {
    sc[threadIdx.x] = 0.f;
}

__global__ void attvec_score_kernel(const float* __restrict__ w_u, const float* __restrict__ w_m,
                                    float* __restrict__ sc) {
    __shared__ float tsm[128];
    int t = threadIdx.x;                       // 128
    int col = (blockIdx.x & 7) * 128 + t;
    int i0 = (blockIdx.x >> 3) * 128;
    tsm[t] = tanhf(w_m[i0 + t]);
    __syncthreads();
    float u = 0.f;
    #pragma unroll 4
    for (int i = 0; i < 128; i++)
        u = fmaf(w_u[(size_t)(i0 + i) * DIM + col], tsm[i], u);
    atomicAdd(&sc[col], u);
}

__global__ void attvec_softmax_kernel(const float* __restrict__ sc, float* __restrict__ att) {
    __shared__ float red[32], bc[1];
    int t = threadIdx.x;  // 1024
    float u = sc[t];
    int lane = t & 31, w = t >> 5;
    float m = u;
    #pragma unroll
    for (int off = 16; off; off >>= 1) m = fmaxf(m, __shfl_xor_sync(~0u, m, off));
    if (lane == 0) red[w] = m;
    __syncthreads();
    if (w == 0) {
        float r = red[lane];
        #pragma unroll
        for (int off = 16; off; off >>= 1) r = fmaxf(r, __shfl_xor_sync(~0u, r, off));
        if (lane == 0) bc[0] = r;
    }
    __syncthreads();
    float gmax = bc[0];
    __syncthreads();
    float e = expf(u - gmax);
    float s = e;
    #pragma unroll
    for (int off = 16; off; off >>= 1) s += __shfl_xor_sync(~0u, s, off);
    if (lane == 0) red[w] = s;
    __syncthreads();
    if (w == 0) {
        float r = red[lane];
        #pragma unroll
        for (int off = 16; off; off >>= 1) r += __shfl_xor_sync(~0u, r, off);
        if (lane == 0) bc[0] = r;
    }
    __syncthreads();
    att[t] = e / bc[0];
}

__global__ void gx_kernel(const float* __restrict__ lstm_in, const float* __restrict__ Wih,
                          const float* __restrict__ bih, const float* __restrict__ bhh,
                          float* __restrict__ gx) {
    int idx = blockIdx.x * blockDim.x + threadIdx.x;
    if (idx >= LAG * 20) return;
    int l = idx / 20, j = idx % 20;
    float s = bih[j] + bhh[j];
    const float* xi = lstm_in + l * 9;
    const float* wr = Wih + j * 9;
    #pragma unroll
    for (int i = 0; i < 9; i++) s = fmaf(wr[i], xi[i], s);
    gx[idx] = s;
}

__global__ void lstm_kernel(const float* __restrict__ gx, const float* __restrict__ Whh,
                            float* __restrict__ hs) {
    int j = threadIdx.x;
    float w0 = 0.f, w1 = 0.f, w2 = 0.f, w3 = 0.f, w4 = 0.f;
    if (j < 20) {
        w0 = Whh[j * 5 + 0]; w1 = Whh[j * 5 + 1]; w2 = Whh[j * 5 + 2];
        w3 = Whh[j * 5 + 3]; w4 = Whh[j * 5 + 4];
    }
    float h0 = 0.f, h1 = 0.f, h2 = 0.f, h3 = 0.f, h4 = 0.f, c = 0.f;
    bool isg = (j >= 10 && j < 15);
    float pre = isg ? 1.0f : 0.5f;
    float pm  = isg ? 1.0f : 0.5f;
    float pb  = isg ? 0.0f : 0.5f;
    float gA = (j < 20) ? gx[j] : 0.f;
    float gB = (j < 20) ? gx[20 + j] : 0.f;
    for (int l = 0; l < LAG; l++) {
        float gN = 0.f;
        if (l + 2 < LAG && j < 20) gN = gx[(l + 2) * 20 + j];
        float g = gA;
        g = fmaf(w0, h0, g); g = fmaf(w1, h1, g); g = fmaf(w2, h2, g);
        g = fmaf(w3, h3, g); g = fmaf(w4, h4, g);
        float a = fmaf(pm, ftanh(pre * g), pb);
        float f_ = __shfl_sync(~0u, a, (j + 5) & 31);
        float g_ = __shfl_sync(~0u, a, (j + 10) & 31);
        float o_ = __shfl_sync(~0u, a, (j + 15) & 31);
        float hv = 0.f;
        if (j < 5) c = fmaf(f_, c, a * g_);
        float tc = ftanh(c);
        if (j < 5) { hv = o_ * tc; hs[l * HID + j] = hv; }
        h0 = __shfl_sync(~0u, hv, 0); h1 = __shfl_sync(~0u, hv, 1);
        h2 = __shfl_sync(~0u, hv, 2); h3 = __shfl_sync(~0u, hv, 3);
        h4 = __shfl_sync(~0u, hv, 4);
        gA = gB; gB = gN;
    }
}

__global__ void head_kernel(const float* __restrict__ lstm_in, const float* __restrict__ hs,
                            const float* __restrict__ Wt, const float* __restrict__ bt,
                            const float* __restrict__ Wa, const float* __restrict__ ba,
                            float* __restrict__ out) {
    int l = blockIdx.x * blockDim.x + threadIdx.x;
    if (l >= LAG) return;
    float f[14];
    #pragma unroll
    for (int i = 0; i < 9; i++) f[i] = lstm_in[l * 9 + i];
    #pragma unroll
    for (int i = 0; i < 5; i++) f[9 + i] = hs[l * HID + i];
    #pragma unroll
    for (int cidx = 0; cidx < NCLS; cidx++) {
        float s = bt[cidx];
        #pragma unroll
        for (int i = 0; i < 14; i++) s = fmaf(f[i], Wt[i * NCLS + cidx], s);
        out[(size_t)l * NCLS + cidx] = s;
    }
    #pragma unroll
    for (int cidx = 0; cidx < NCLS; cidx++) {
        float s = ba[cidx];
        #pragma unroll
        for (int i = 0; i < 14; i++) s = fmaf(f[i], Wa[i * NCLS + cidx], s);
        out[(size_t)LAG * NCLS + (size_t)l * NCLS + cidx] = s;
    }
}

extern "C" void kernel_launch(void* const* d_in, const int* in_sizes, int n_in,
                              void* d_out, int out_size) {
    const float* text      = (const float*)d_in[0];
    const float* prices    = (const float*)d_in[1];
    const float* pos_embed = (const float*)d_in[2];
    const float* Wq1 = (const float*)d_in[3];
    const float* Wk1 = (const float*)d_in[4];
    const float* Wv1 = (const float*)d_in[5];
    const float* Wo1 = (const float*)d_in[6];
    const float* ln_g = (const float*)d_in[7];
    const float* ln_b = (const float*)d_in[8];
    const float* W1 = (const float*)d_in[9];
    const float* b1 = (const float*)d_in[10];
    const float* W2 = (const float*)d_in[11];
    const float* b2 = (const float*)d_in[12];
    const float* Wq2 = (const float*)d_in[13];
    const float* Wk2 = (const float*)d_in[14];
    const float* Wv2 = (const float*)d_in[15];
    const float* Wo2 = (const float*)d_in[16];
    const float* w_u = (const float*)d_in[17];
    const float* w_m = (const float*)d_in[18];
    const float* Wih = (const float*)d_in[19];
    const float* Whh = (const float*)d_in[20];
    const float* bih = (const float*)d_in[21];
    const float* bhh = (const float*)d_in[22];
    const float* Wt = (const float*)d_in[23];
    const float* bt = (const float*)d_in[24];
    const float* Wa = (const float*)d_in[25];
    const float* ba = (const float*)d_in[26];
    float* out = (float*)d_out;

    float *B0, *B1, *B2, *B3, *B4, *B5, *B6, *WR, *TK2, *MB, *ATSC;
    float *attv, *w1v, *uv, *lstm_in, *gx, *hs;
    cudaGetSymbolAddress((void**)&B0, g_buf0);
    cudaGetSymbolAddress((void**)&B1, g_buf1);
    cudaGetSymbolAddress((void**)&B2, g_buf2);
    cudaGetSymbolAddress((void**)&B3, g_buf3);
    cudaGetSymbolAddress((void**)&B4, g_buf4);
    cudaGetSymbolAddress((void**)&B5, g_buf5);
    cudaGetSymbolAddress((void**)&B6, g_buf6);
    cudaGetSymbolAddress((void**)&WR, g_wr);
    cudaGetSymbolAddress((void**)&TK2, g_tk2);
    cudaGetSymbolAddress((void**)&MB, g_m);
    cudaGetSymbolAddress((void**)&ATSC, g_attsc);
    cudaGetSymbolAddress((void**)&attv, g_attv);
    cudaGetSymbolAddress((void**)&w1v, g_w1);
    cudaGetSymbolAddress((void**)&uv, g_u);
    cudaGetSymbolAddress((void**)&lstm_in, g_lstm_in);
    cudaGetSymbolAddress((void**)&gx, g_gx);
    cudaGetSymbolAddress((void**)&hs, g_hs);

    cudaFuncSetAttribute(tgemm_kernel<0>, cudaFuncAttributeMaxDynamicSharedMemorySize, GEMM_SMEM);
    cudaFuncSetAttribute(tgemm_kernel<1>, cudaFuncAttributeMaxDynamicSharedMemorySize, GEMM_SMEM);
    cudaFuncSetAttribute(tgemm_kernel<2>, cudaFuncAttributeMaxDynamicSharedMemorySize, GEMM_SMEM);
    cudaFuncSetAttribute(tgemm_kernel<3>, cudaFuncAttributeMaxDynamicSharedMemorySize, GEMM_SMEM);

    const size_t WSZ = (size_t)DIM * DIM;
    float* Rq1 = WR + 0 * WSZ; float* Rk1 = WR + 1 * WSZ;
    float* Rv1 = WR + 2 * WSZ; float* Ro1 = WR + 3 * WSZ;
    float* R1  = WR + 4 * WSZ; float* R2  = WR + 5 * WSZ;
    float* Rq2 = WR + 6 * WSZ;

    dim3 ggrid(DIM / BN, MROWS / BM);    // (4, 256)
    dim3 mgrid(DIM / BN, DIM / BM);      // (4, 8)
    dim3 wgrid(128, 7);
    dim3 tgrid(32, 32), tblk(32, 8);

    // prep
    wprep_kernel<<<wgrid, 256>>>(Wq1, Wk1, Wv1, Wo1, W1, W2, Wq2, WR);
    transpose_kernel<<<tgrid, tblk>>>(Wk2, TK2);
    attvec_zero_kernel<<<1, 1024>>>(ATSC);
    attvec_score_kernel<<<64, 128>>>(w_u, w_m, ATSC);
    attvec_softmax_kernel<<<1, 1024>>>(ATSC, attv);
    matvec_kernel<<<DIM, 128>>>(Wo2, attv, w1v);
    matvec_kernel<<<DIM, 128>>>(Wv2, w1v, uv);
    tgemm_kernel<3><<<mgrid, 256, GEMM_SMEM>>>(Rq2, TK2, nullptr, MB);

    // x = text + pos (B0 full, B6 rounded)
    add_kernel<<<4096, 256>>>(text, pos_embed, B0, B6, NELEM / 4);

    // MHA1
    tgemm_kernel<0><<<ggrid, 256, GEMM_SMEM>>>(B6, Rq1, nullptr, B1);
    tgemm_kernel<0><<<ggrid, 256, GEMM_SMEM>>>(B6, Rk1, nullptr, B2);
    tgemm_kernel<0><<<ggrid, 256, GEMM_SMEM>>>(B6, Rv1, nullptr, B3);
    attn1_kernel<<<LAG, 256>>>(B1, B2, B3, B4);
    tgemm_kernel<0><<<ggrid, 256, GEMM_SMEM>>>(B4, Ro1, nullptr, B5);

    // residual + LN
    ln_kernel<<<MROWS, 256>>>(B5, B0, ln_g, ln_b, B1);

    // FFN (B3 = ffn output, rounded)
    tgemm_kernel<1><<<ggrid, 256, GEMM_SMEM>>>(B1, R1, b1, B2);
    tgemm_kernel<2><<<ggrid, 256, GEMM_SMEM>>>(B2, R2, b2, B3);

    // MHA2 collapsed: T = ffn @ M, then fused attention + pooling
    tgemm_kernel<0><<<ggrid, 256, GEMM_SMEM>>>(B3, MB, nullptr, B0);
    attn2pool_kernel<<<LAG, 512>>>(B0, B3, uv, prices, lstm_in);

    // LSTM + heads
    gx_kernel<<<(LAG * 20 + 255) / 256, 256>>>(lstm_in, Wih, bih, bhh, gx);
    lstm_kernel<<<1, 32>>>(gx, Whh, hs);
    head_kernel<<<(LAG + 255) / 256, 256>>>(lstm_in, hs, Wt, bt, Wa, ba, out);
}

// round 17
// speedup vs baseline: 1.4388x; 1.2125x over previous
#include <cuda_runtime.h>
#include <math.h>
#include <stdint.h>

#define LAG   8192
#define KTOK  4
#define DIM   1024
#define HEADS 16
#define DH    64
#define HID   5
#define NCLS  2
#define MROWS (LAG * KTOK)
#define NELEM (MROWS * DIM)

// LSTM speculative-parallel parameters
#define LCHUNK  128
#define LWARMUP 384
#define LNCHUNK (LAG / LCHUNK)   // 64

__device__ float g_buf0[NELEM];
__device__ float g_buf1[NELEM];
__device__ float g_buf2[NELEM];
__device__ float g_buf3[NELEM];
__device__ float g_buf4[NELEM];
__device__ float g_buf5[NELEM];
__device__ float g_buf6[NELEM];           // rounded copy of x
__device__ float g_wr[7 * DIM * DIM];     // rounded Rq1,Rk1,Rv1,Ro1,R1,R2,Rq2
__device__ float g_tk2[DIM * DIM];
__device__ float g_m[DIM * DIM];          // M = Wq2 @ Wk2^T (rounded)
__device__ float g_attsc[DIM];
__device__ float g_attv[DIM];
__device__ float g_w1[DIM];
__device__ float g_u[DIM];
__device__ float g_lstm_in[LAG * 9];
__device__ float g_gx[LAG * 20];
__device__ float g_hs[LAG * HID];

__device__ __forceinline__ uint32_t smem_u32(const void* p) {
    return (uint32_t)__cvta_generic_to_shared(p);
}
__device__ __forceinline__ float rnd_tf32(float x) {
    uint32_t r; asm("cvt.rna.tf32.f32 %0, %1;" : "=r"(r) : "f"(x));
    return __uint_as_float(r);
}
__device__ __forceinline__ void cpa16(uint32_t dst, const void* src) {
    asm volatile("cp.async.cg.shared.global [%0], [%1], 16;" :: "r"(dst), "l"(src));
}
__device__ __forceinline__ float ftanh(float x) {
    float y; asm("tanh.approx.f32 %0, %1;" : "=f"(y) : "f"(x)); return y;
}
__device__ __forceinline__ void mma_t(float* d, const uint32_t* a, const uint32_t* b) {
    asm volatile(
        "mma.sync.aligned.m16n8k8.row.col.f32.tf32.tf32.f32 "
        "{%0,%1,%2,%3}, {%4,%5,%6,%7}, {%8,%9}, {%0,%1,%2,%3};"
        : "+f"(d[0]), "+f"(d[1]), "+f"(d[2]), "+f"(d[3])
        : "r"(a[0]), "r"(a[1]), "r"(a[2]), "r"(a[3]), "r"(b[0]), "r"(b[1]));
}

// ------- tf32 mma.sync GEMM (round-8/14 proven): C[M,1024] = A @ W -------
#define BM 128
#define BN 256
#define BK 32
#define KITER 32
#define NST 4
#define AST 36
#define BST 260
#define A_STG (BM * AST)
#define B_STG (BK * BST)
#define GEMM_SMEM ((NST * (A_STG + B_STG)) * 4)

__device__ __forceinline__ void g_load(const float* __restrict__ A,
                                       const float* __restrict__ W,
                                       int bm, int kt, int bn,
                                       float* as, float* bs, int tid) {
    float* ab = as + (kt & 3) * A_STG;
    float* bb = bs + (kt & 3) * B_STG;
    int k0 = kt * BK;
    #pragma unroll
    for (int c = tid; c < 1024; c += 256) {
        int m = c >> 3, kq = c & 7;
        cpa16(smem_u32(ab + m * AST + kq * 4),
              A + (size_t)(bm + m) * 1024 + k0 + kq * 4);
    }
    #pragma unroll
    for (int c = tid; c < 2048; c += 256) {
        int k = c >> 6, nq = c & 63;
        cpa16(smem_u32(bb + k * BST + nq * 4),
              W + (size_t)(k0 + k) * 1024 + bn + nq * 4);
    }
    asm volatile("cp.async.commit_group;" ::: "memory");
}

__device__ __forceinline__ void frag_load(const float* ab, const float* bb,
                                          int wm, int wn, int g, int t, int ks,
                                          uint32_t af[4][4], uint32_t bf[8][2]) {
    #pragma unroll
    for (int mi = 0; mi < 4; mi++) {
        const uint32_t* ap = (const uint32_t*)(ab + (wm + mi * 16 + g) * AST + ks * 8 + t);
        af[mi][0] = ap[0];
        af[mi][1] = ap[8 * AST];
        af[mi][2] = ap[4];
        af[mi][3] = ap[8 * AST + 4];
    }
    #pragma unroll
    for (int ni = 0; ni < 8; ni++) {
        const uint32_t* bp = (const uint32_t*)(bb + (ks * 8 + t) * BST + wn + ni * 8 + g);
        bf[ni][0] = bp[0];
        bf[ni][1] = bp[4 * BST];
    }
}

// MODE 0: plain; 1: +bias+relu+rnd; 2: +bias+rnd; 3: +rnd
template<int MODE>
__global__ void __launch_bounds__(256, 1)
tgemm_kernel(const float* __restrict__ A, const float* __restrict__ W,
             const float* __restrict__ bias, float* __restrict__ C) {
    extern __shared__ float sb[];
    float* as = sb;
    float* bs = sb + NST * A_STG;

    int tid = threadIdx.x;
    int wid = tid >> 5, lane = tid & 31;
    int g = lane >> 2, t = lane & 3;
    int bm = blockIdx.y * BM, bn = blockIdx.x * BN;
    int wm = (wid >> 2) * 64;
    int wn = (wid & 3) * 64;

    float acc[4][8][4];
    #pragma unroll
    for (int i = 0; i < 4; i++)
        #pragma unroll
        for (int j = 0; j < 8; j++)
            #pragma unroll
            for (int r = 0; r < 4; r++) acc[i][j][r] = 0.f;

    g_load(A, W, bm, 0, bn, as, bs, tid);
    g_load(A, W, bm, 1, bn, as, bs, tid);

    uint32_t af[2][4][4], bf[2][8][2];

    for (int kt = 0; kt < KITER; kt++) {
        if (kt + 2 < KITER) {
            g_load(A, W, bm, kt + 2, bn, as, bs, tid);
            asm volatile("cp.async.wait_group 2;" ::: "memory");
        } else if (kt == KITER - 2) {
            asm volatile("cp.async.wait_group 1;" ::: "memory");
        } else {
            asm volatile("cp.async.wait_group 0;" ::: "memory");
        }
        __syncthreads();

        const float* ab = as + (kt & 3) * A_STG;
        const float* bb = bs + (kt & 3) * B_STG;

        frag_load(ab, bb, wm, wn, g, t, 0, af[0], bf[0]);
        #pragma unroll
        for (int ks = 0; ks < 4; ks++) {
            int cur = ks & 1;
            if (ks < 3)
                frag_load(ab, bb, wm, wn, g, t, ks + 1, af[cur ^ 1], bf[cur ^ 1]);
            #pragma unroll
            for (int mi = 0; mi < 4; mi++)
                #pragma unroll
                for (int ni = 0; ni < 8; ni++)
                    mma_t(acc[mi][ni], af[cur][mi], bf[cur][ni]);
        }
    }

    #pragma unroll
    for (int mi = 0; mi < 4; mi++) {
        #pragma unroll
        for (int ni = 0; ni < 8; ni++) {
            int row = bm + wm + mi * 16 + g;
            int col = bn + wn + ni * 8 + 2 * t;
            float2 v0 = make_float2(acc[mi][ni][0], acc[mi][ni][1]);
            float2 v1 = make_float2(acc[mi][ni][2], acc[mi][ni][3]);
            if (MODE == 1 || MODE == 2) {
                float b0 = bias[col], b1 = bias[col + 1];
                v0.x += b0; v0.y += b1; v1.x += b0; v1.y += b1;
                if (MODE == 1) {
                    v0.x = fmaxf(v0.x, 0.f); v0.y = fmaxf(v0.y, 0.f);
                    v1.x = fmaxf(v1.x, 0.f); v1.y = fmaxf(v1.y, 0.f);
                }
            }
            if (MODE != 0) {
                v0.x = rnd_tf32(v0.x); v0.y = rnd_tf32(v0.y);
                v1.x = rnd_tf32(v1.x); v1.y = rnd_tf32(v1.y);
            }
            *(float2*)&C[(size_t)row * 1024 + col] = v0;
            *(float2*)&C[(size_t)(row + 8) * 1024 + col] = v1;
        }
    }
}

// round 7 matrices: Rq1, Rk1, Rv1, Ro1, R1, R2, Rq2
__global__ void wprep_kernel(const float* __restrict__ w0, const float* __restrict__ w1,
                             const float* __restrict__ w2, const float* __restrict__ w3,
                             const float* __restrict__ w4, const float* __restrict__ w5,
                             const float* __restrict__ w6,
                             float* __restrict__ dst) {
    const float* srcs[7] = {w0, w1, w2, w3, w4, w5, w6};
    int wsel = blockIdx.y;
    const float4* s = (const float4*)srcs[wsel];
    float4* d = (float4*)(dst + (size_t)wsel * DIM * DIM);
    int n4 = DIM * DIM / 4;
    for (int i = blockIdx.x * blockDim.x + threadIdx.x; i < n4; i += gridDim.x * blockDim.x) {
        float4 v = s[i];
        v.x = rnd_tf32(v.x); v.y = rnd_tf32(v.y);
        v.z = rnd_tf32(v.z); v.w = rnd_tf32(v.w);
        d[i] = v;
    }
}

__global__ void transpose_kernel(const float* __restrict__ in, float* __restrict__ out) {
    __shared__ float t[32][33];
    int bx = blockIdx.x * 32, by = blockIdx.y * 32;
    #pragma unroll
    for (int j = 0; j < 32; j += 8)
        t[threadIdx.y + j][threadIdx.x] = in[(size_t)(by + threadIdx.y + j) * DIM + bx + threadIdx.x];
    __syncthreads();
    #pragma unroll
    for (int j = 0; j < 32; j += 8)
        out[(size_t)(bx + threadIdx.y + j) * DIM + by + threadIdx.x] =
            rnd_tf32(t[threadIdx.x][threadIdx.y + j]);
}

__global__ void matvec_kernel(const float* __restrict__ W, const float* __restrict__ v,
                              float* __restrict__ out) {
    int row = blockIdx.x;
    int t = threadIdx.x;  // 128
    __shared__ float red[4];
    const float4* wp = (const float4*)(W + (size_t)row * DIM);
    const float4* vp = (const float4*)v;
    float s = 0.f;
    for (int j = t; j < 256; j += 128) {
        float4 a = wp[j], b = vp[j];
        s = fmaf(a.x, b.x, s); s = fmaf(a.y, b.y, s);
        s = fmaf(a.z, b.z, s); s = fmaf(a.w, b.w, s);
    }
    int lane = t & 31, w = t >> 5;
    #pragma unroll
    for (int off = 16; off; off >>= 1) s += __shfl_xor_sync(~0u, s, off);
    if (lane == 0) red[w] = s;
    __syncthreads();
    if (t == 0) out[row] = red[0] + red[1] + red[2] + red[3];
}

__global__ void add_kernel(const float* __restrict__ a, const float* __restrict__ b,
                           float* __restrict__ cf, float* __restrict__ cr, int n4) {
    int i = blockIdx.x * blockDim.x + threadIdx.x;
    int stride = gridDim.x * blockDim.x;
    const float4* a4 = (const float4*)a;
    const float4* b4 = (const float4*)b;
    float4* c4 = (float4*)cf;
    float4* r4 = (float4*)cr;
    for (; i < n4; i += stride) {
        float4 x = a4[i], y = b4[i];
        x.x += y.x; x.y += y.y; x.z += y.z; x.w += y.w;
        c4[i] = x;
        float4 r;
        r.x = rnd_tf32(x.x); r.y = rnd_tf32(x.y);
        r.z = rnd_tf32(x.z); r.w = rnd_tf32(x.w);
        r4[i] = r;
    }
}

__global__ void attn1_kernel(const float* __restrict__ q, const float* __restrict__ k,
                             const float* __restrict__ v, float* __restrict__ o) {
    int l = blockIdx.x;
    int t = threadIdx.x;  // 256
    __shared__ float a_s[HEADS][KTOK][KTOK];
    int h = t >> 4, qt = (t >> 2) & 3, kt = t & 3;
    const float4* qp = (const float4*)(q + (size_t)(l * 4 + qt) * DIM + h * DH);
    const float4* kp = (const float4*)(k + (size_t)(l * 4 + kt) * DIM + h * DH);
    float s = 0.f;
    #pragma unroll
    for (int j = 0; j < 16; j++) {
        float4 a = qp[j], b = kp[j];
        s = fmaf(a.x, b.x, s); s = fmaf(a.y, b.y, s);
        s = fmaf(a.z, b.z, s); s = fmaf(a.w, b.w, s);
    }
    s *= 0.125f;
    float m = fmaxf(s, __shfl_xor_sync(~0u, s, 1));
    m = fmaxf(m, __shfl_xor_sync(~0u, m, 2));
    float e = expf(s - m);
    float se = e + __shfl_xor_sync(~0u, e, 1);
    se += __shfl_xor_sync(~0u, se, 2);
    a_s[h][qt][kt] = e / se;
    __syncthreads();
    #pragma unroll
    for (int it = 0; it < 16; it++) {
        int idx = it * 256 + t;
        int qq = idx >> 10, d = idx & 1023, hh = d >> 6;
        float acc = 0.f;
        #pragma unroll
        for (int kk = 0; kk < 4; kk++)
            acc = fmaf(a_s[hh][qq][kk], v[(size_t)(l * 4 + kk) * DIM + d], acc);
        o[(size_t)(l * 4 + qq) * DIM + d] = rnd_tf32(acc);
    }
}

__global__ void ln_kernel(const float* __restrict__ inter, const float* __restrict__ x,
                          const float* __restrict__ g, const float* __restrict__ b,
                          float* __restrict__ y) {
    int row = blockIdx.x;
    int t = threadIdx.x;  // 256
    __shared__ float red1[32], red2[32], bc[2];
    const float4* pi = (const float4*)(inter + (size_t)row * DIM);
    const float4* px = (const float4*)(x + (size_t)row * DIM);
    float4 vi = pi[t], vx = px[t];
    float v0 = vi.x + vx.x, v1 = vi.y + vx.y, v2 = vi.z + vx.z, v3 = vi.w + vx.w;
    float sum = v0 + v1 + v2 + v3;
    float sq = v0 * v0 + v1 * v1 + v2 * v2 + v3 * v3;
    int lane = t & 31, w = t >> 5;
    #pragma unroll
    for (int off = 16; off; off >>= 1) {
        sum += __shfl_xor_sync(~0u, sum, off);
        sq  += __shfl_xor_sync(~0u, sq, off);
    }
    if (lane == 0) { red1[w] = sum; red2[w] = sq; }
    __syncthreads();
    if (w == 0) {
        float r1 = (lane < 8) ? red1[lane] : 0.f;
        float r2 = (lane < 8) ? red2[lane] : 0.f;
        #pragma unroll
        for (int off = 4; off; off >>= 1) {
            r1 += __shfl_xor_sync(~0u, r1, off);
            r2 += __shfl_xor_sync(~0u, r2, off);
        }
        if (lane == 0) { bc[0] = r1; bc[1] = r2; }
    }
    __syncthreads();
    float mean = bc[0] * (1.0f / DIM);
    float var = bc[1] * (1.0f / DIM) - mean * mean;
    float inv = rsqrtf(var + 1e-5f);
    int c = t * 4;
    float4 out;
    out.x = rnd_tf32((v0 - mean) * inv * g[c + 0] + b[c + 0]);
    out.y = rnd_tf32((v1 - mean) * inv * g[c + 1] + b[c + 1]);
    out.z = rnd_tf32((v2 - mean) * inv * g[c + 2] + b[c + 2]);
    out.w = rnd_tf32((v3 - mean) * inv * g[c + 3] + b[c + 3]);
    *(float4*)(y + (size_t)row * DIM + c) = out;
}

// fused attn2 + pooling
__global__ void attn2pool_kernel(const float* __restrict__ T, const float* __restrict__ ffn,
                                 const float* __restrict__ u, const float* __restrict__ prices,
                                 float* __restrict__ lstm_in) {
    int l = blockIdx.x;
    int t = threadIdx.x;  // 512
    int w = t >> 5, lane = t & 31;
    __shared__ float s_s[KTOK][KTOK], fk_s[KTOK];
    if (w < 16) {
        int qt = w >> 2, kt = w & 3;
        const float4* qp = (const float4*)(T + (size_t)(l * 4 + qt) * DIM);
        const float4* kp = (const float4*)(ffn + (size_t)(l * 4 + kt) * DIM);
        const float4* up = (const float4*)u;
        float s = 0.f, s2 = 0.f;
        for (int j = lane; j < 256; j += 32) {
            float4 a = qp[j], b = kp[j];
            s = fmaf(a.x, b.x, s); s = fmaf(a.y, b.y, s);
            s = fmaf(a.z, b.z, s); s = fmaf(a.w, b.w, s);
            if (qt == 0) {
                float4 uu = up[j];
                s2 = fmaf(b.x, uu.x, s2); s2 = fmaf(b.y, uu.y, s2);
                s2 = fmaf(b.z, uu.z, s2); s2 = fmaf(b.w, uu.w, s2);
            }
        }
        #pragma unroll
        for (int off = 16; off; off >>= 1) {
            s  += __shfl_xor_sync(~0u, s, off);
            s2 += __shfl_xor_sync(~0u, s2, off);
        }
        if (lane == 0) {
            s_s[qt][kt] = s * (1.0f / 32.0f);
            if (qt == 0) fk_s[kt] = s2;
        }
    }
    __syncthreads();
    if (t < 4) {
        float m = -1e30f;
        #pragma unroll
        for (int kk = 0; kk < 4; kk++) m = fmaxf(m, s_s[t][kk]);
        float sum = 0.f, acc = 0.f;
        #pragma unroll
        for (int kk = 0; kk < 4; kk++) {
            float e = expf(s_s[t][kk] - m);
            sum += e;
            acc = fmaf(e, fk_s[kk], acc);
        }
        lstm_in[l * 9 + t] = acc / sum;
    }
    if (t >= 8 && t < 13) lstm_in[l * 9 + 4 + (t - 8)] = prices[l * 5 + (t - 8)];
}

// attvec three-stage
__global__ void attvec_zero_kernel(float* __restrict__ sc) {
    sc[threadIdx.x] = 0.f;
}

__global__ void attvec_score_kernel(const float* __restrict__ w_u, const float* __restrict__ w_m,
                                    float* __restrict__ sc) {
    __shared__ float tsm[128];
    int t = threadIdx.x;                       // 128
    int col = (blockIdx.x & 7) * 128 + t;
    int i0 = (blockIdx.x >> 3) * 128;
    tsm[t] = tanhf(w_m[i0 + t]);
    __syncthreads();
    float u = 0.f;
    #pragma unroll 4
    for (int i = 0; i < 128; i++)
        u = fmaf(w_u[(size_t)(i0 + i) * DIM + col], tsm[i], u);
    atomicAdd(&sc[col], u);
}

__global__ void attvec_softmax_kernel(const float* __restrict__ sc, float* __restrict__ att) {
    __shared__ float red[32], bc[1];
    int t = threadIdx.x;  // 1024
    float u = sc[t];
    int lane = t & 31, w = t >> 5;
    float m = u;
    #pragma unroll
    for (int off = 16; off; off >>= 1) m = fmaxf(m, __shfl_xor_sync(~0u, m, off));
    if (lane == 0) red[w] = m;
    __syncthreads();
    if (w == 0) {
        float r = red[lane];
        #pragma unroll
        for (int off = 16; off; off >>= 1) r = fmaxf(r, __shfl_xor_sync(~0u, r, off));
        if (lane == 0) bc[0] = r;
    }
    __syncthreads();
    float gmax = bc[0];
    __syncthreads();
    float e = expf(u - gmax);
    float s = e;
    #pragma unroll
    for (int off = 16; off; off >>= 1) s += __shfl_xor_sync(~0u, s, off);
    if (lane == 0) red[w] = s;
    __syncthreads();
    if (w == 0) {
        float r = red[lane];
        #pragma unroll
        for (int off = 16; off; off >>= 1) r += __shfl_xor_sync(~0u, r, off);
        if (lane == 0) bc[0] = r;
    }
    __syncthreads();
    att[t] = e / bc[0];
}

__global__ void gx_kernel(const float* __restrict__ lstm_in, const float* __restrict__ Wih,
                          const float* __restrict__ bih, const float* __restrict__ bhh,
                          float* __restrict__ gx) {
    int idx = blockIdx.x * blockDim.x + threadIdx.x;
    if (idx >= LAG * 20) return;
    int l = idx / 20, j = idx % 20;
    float s = bih[j] + bhh[j];
    const float* xi = lstm_in + l * 9;
    const float* wr = Wih + j * 9;
    #pragma unroll
    for (int i = 0; i < 9; i++) s = fmaf(wr[i], xi[i], s);
    gx[idx] = s;
}

// speculative-parallel LSTM: 64 chunks of 128 steps, each warp starts from zero
// state LWARMUP steps early; contraction makes the warmup-converged state match
// the exact sequential state to below fp32 epsilon. Chunk 0 is exact.
__global__ void lstm_kernel(const float* __restrict__ gx, const float* __restrict__ Whh,
                            float* __restrict__ hs) {
    int j = threadIdx.x;
    int chunk = blockIdx.x;
    int real0 = chunk * LCHUNK;
    int start = real0 - LWARMUP;
    if (start < 0) start = 0;
    int end = real0 + LCHUNK;

    float w0 = 0.f, w1 = 0.f, w2 = 0.f, w3 = 0.f, w4 = 0.f;
    if (j < 20) {
        w0 = Whh[j * 5 + 0]; w1 = Whh[j * 5 + 1]; w2 = Whh[j * 5 + 2];
        w3 = Whh[j * 5 + 3]; w4 = Whh[j * 5 + 4];
    }
    float h0 = 0.f, h1 = 0.f, h2 = 0.f, h3 = 0.f, h4 = 0.f, c = 0.f;
    bool isg = (j >= 10 && j < 15);
    float pre = isg ? 1.0f : 0.5f;
    float pm  = isg ? 1.0f : 0.5f;
    float pb  = isg ? 0.0f : 0.5f;
    float gA = (j < 20) ? gx[start * 20 + j] : 0.f;
    float gB = (j < 20) ? gx[(start + 1) * 20 + j] : 0.f;
    for (int l = start; l < end; l++) {
        float gN = 0.f;
        if (l + 2 < LAG && j < 20) gN = gx[(l + 2) * 20 + j];
        float g = gA;
        g = fmaf(w0, h0, g); g = fmaf(w1, h1, g); g = fmaf(w2, h2, g);
        g = fmaf(w3, h3, g); g = fmaf(w4, h4, g);
        float a = fmaf(pm, ftanh(pre * g), pb);
        float f_ = __shfl_sync(~0u, a, (j + 5) & 31);
        float g_ = __shfl_sync(~0u, a, (j + 10) & 31);
        float o_ = __shfl_sync(~0u, a, (j + 15) & 31);
        float hv = 0.f;
        if (j < 5) c = fmaf(f_, c, a * g_);
        float tc = ftanh(c);
        if (j < 5) {
            hv = o_ * tc;
            if (l >= real0) hs[l * HID + j] = hv;
        }
        h0 = __shfl_sync(~0u, hv, 0); h1 = __shfl_sync(~0u, hv, 1);
        h2 = __shfl_sync(~0u, hv, 2); h3 = __shfl_sync(~0u, hv, 3);
        h4 = __shfl_sync(~0u, hv, 4);
        gA = gB; gB = gN;
    }
}

__global__ void head_kernel(const float* __restrict__ lstm_in, const float* __restrict__ hs,
                            const float* __restrict__ Wt, const float* __restrict__ bt,
                            const float* __restrict__ Wa, const float* __restrict__ ba,
                            float* __restrict__ out) {
    int l = blockIdx.x * blockDim.x + threadIdx.x;
    if (l >= LAG) return;
    float f[14];
    #pragma unroll
    for (int i = 0; i < 9; i++) f[i] = lstm_in[l * 9 + i];
    #pragma unroll
    for (int i = 0; i < 5; i++) f[9 + i] = hs[l * HID + i];
    #pragma unroll
    for (int cidx = 0; cidx < NCLS; cidx++) {
        float s = bt[cidx];
        #pragma unroll
        for (int i = 0; i < 14; i++) s = fmaf(f[i], Wt[i * NCLS + cidx], s);
        out[(size_t)l * NCLS + cidx] = s;
    }
    #pragma unroll
    for (int cidx = 0; cidx < NCLS; cidx++) {
        float s = ba[cidx];
        #pragma unroll
        for (int i = 0; i < 14; i++) s = fmaf(f[i], Wa[i * NCLS + cidx], s);
        out[(size_t)LAG * NCLS + (size_t)l * NCLS + cidx] = s;
    }
}

extern "C" void kernel_launch(void* const* d_in, const int* in_sizes, int n_in,
                              void* d_out, int out_size) {
    const float* text      = (const float*)d_in[0];
    const float* prices    = (const float*)d_in[1];
    const float* pos_embed = (const float*)d_in[2];
    const float* Wq1 = (const float*)d_in[3];
    const float* Wk1 = (const float*)d_in[4];
    const float* Wv1 = (const float*)d_in[5];
    const float* Wo1 = (const float*)d_in[6];
    const float* ln_g = (const float*)d_in[7];
    const float* ln_b = (const float*)d_in[8];
    const float* W1 = (const float*)d_in[9];
    const float* b1 = (const float*)d_in[10];
    const float* W2 = (const float*)d_in[11];
    const float* b2 = (const float*)d_in[12];
    const float* Wq2 = (const float*)d_in[13];
    const float* Wk2 = (const float*)d_in[14];
    const float* Wv2 = (const float*)d_in[15];
    const float* Wo2 = (const float*)d_in[16];
    const float* w_u = (const float*)d_in[17];
    const float* w_m = (const float*)d_in[18];
    const float* Wih = (const float*)d_in[19];
    const float* Whh = (const float*)d_in[20];
    const float* bih = (const float*)d_in[21];
    const float* bhh = (const float*)d_in[22];
    const float* Wt = (const float*)d_in[23];
    const float* bt = (const float*)d_in[24];
    const float* Wa = (const float*)d_in[25];
    const float* ba = (const float*)d_in[26];
    float* out = (float*)d_out;

    float *B0, *B1, *B2, *B3, *B4, *B5, *B6, *WR, *TK2, *MB, *ATSC;
    float *attv, *w1v, *uv, *lstm_in, *gx, *hs;
    cudaGetSymbolAddress((void**)&B0, g_buf0);
    cudaGetSymbolAddress((void**)&B1, g_buf1);
    cudaGetSymbolAddress((void**)&B2, g_buf2);
    cudaGetSymbolAddress((void**)&B3, g_buf3);
    cudaGetSymbolAddress((void**)&B4, g_buf4);
    cudaGetSymbolAddress((void**)&B5, g_buf5);
    cudaGetSymbolAddress((void**)&B6, g_buf6);
    cudaGetSymbolAddress((void**)&WR, g_wr);
    cudaGetSymbolAddress((void**)&TK2, g_tk2);
    cudaGetSymbolAddress((void**)&MB, g_m);
    cudaGetSymbolAddress((void**)&ATSC, g_attsc);
    cudaGetSymbolAddress((void**)&attv, g_attv);
    cudaGetSymbolAddress((void**)&w1v, g_w1);
    cudaGetSymbolAddress((void**)&uv, g_u);
    cudaGetSymbolAddress((void**)&lstm_in, g_lstm_in);
    cudaGetSymbolAddress((void**)&gx, g_gx);
    cudaGetSymbolAddress((void**)&hs, g_hs);

    cudaFuncSetAttribute(tgemm_kernel<0>, cudaFuncAttributeMaxDynamicSharedMemorySize, GEMM_SMEM);
    cudaFuncSetAttribute(tgemm_kernel<1>, cudaFuncAttributeMaxDynamicSharedMemorySize, GEMM_SMEM);
    cudaFuncSetAttribute(tgemm_kernel<2>, cudaFuncAttributeMaxDynamicSharedMemorySize, GEMM_SMEM);
    cudaFuncSetAttribute(tgemm_kernel<3>, cudaFuncAttributeMaxDynamicSharedMemorySize, GEMM_SMEM);

    const size_t WSZ = (size_t)DIM * DIM;
    float* Rq1 = WR + 0 * WSZ; float* Rk1 = WR + 1 * WSZ;
    float* Rv1 = WR + 2 * WSZ; float* Ro1 = WR + 3 * WSZ;
    float* R1  = WR + 4 * WSZ; float* R2  = WR + 5 * WSZ;
    float* Rq2 = WR + 6 * WSZ;

    dim3 ggrid(DIM / BN, MROWS / BM);    // (4, 256)
    dim3 mgrid(DIM / BN, DIM / BM);      // (4, 8)
    dim3 wgrid(128, 7);
    dim3 tgrid(32, 32), tblk(32, 8);

    // prep
    wprep_kernel<<<wgrid, 256>>>(Wq1, Wk1, Wv1, Wo1, W1, W2, Wq2, WR);
    transpose_kernel<<<tgrid, tblk>>>(Wk2, TK2);
    attvec_zero_kernel<<<1, 1024>>>(ATSC);
    attvec_score_kernel<<<64, 128>>>(w_u, w_m, ATSC);
    attvec_softmax_kernel<<<1, 1024>>>(ATSC, attv);
    matvec_kernel<<<DIM, 128>>>(Wo2, attv, w1v);
    matvec_kernel<<<DIM, 128>>>(Wv2, w1v, uv);
    tgemm_kernel<3><<<mgrid, 256, GEMM_SMEM>>>(Rq2, TK2, nullptr, MB);

    // x = text + pos (B0 full, B6 rounded)
    add_kernel<<<4096, 256>>>(text, pos_embed, B0, B6, NELEM / 4);

    // MHA1
    tgemm_kernel<0><<<ggrid, 256, GEMM_SMEM>>>(B6, Rq1, nullptr, B1);
    tgemm_kernel<0><<<ggrid, 256, GEMM_SMEM>>>(B6, Rk1, nullptr, B2);
    tgemm_kernel<0><<<ggrid, 256, GEMM_SMEM>>>(B6, Rv1, nullptr, B3);
    attn1_kernel<<<LAG, 256>>>(B1, B2, B3, B4);
    tgemm_kernel<0><<<ggrid, 256, GEMM_SMEM>>>(B4, Ro1, nullptr, B5);

    // residual + LN
    ln_kernel<<<MROWS, 256>>>(B5, B0, ln_g, ln_b, B1);

    // FFN (B3 = ffn output, rounded)
    tgemm_kernel<1><<<ggrid, 256, GEMM_SMEM>>>(B1, R1, b1, B2);
    tgemm_kernel<2><<<ggrid, 256, GEMM_SMEM>>>(B2, R2, b2, B3);

    // MHA2 collapsed: T = ffn @ M, then fused attention + pooling
    tgemm_kernel<0><<<ggrid, 256, GEMM_SMEM>>>(B3, MB, nullptr, B0);
    attn2pool_kernel<<<LAG, 512>>>(B0, B3, uv, prices, lstm_in);

    // LSTM (speculative-parallel) + heads
    gx_kernel<<<(LAG * 20 + 255) / 256, 256>>>(lstm_in, Wih, bih, bhh, gx);
    lstm_kernel<<<LNCHUNK, 32>>>(gx, Whh, hs);
    head_kernel<<<(LAG + 255) / 256, 256>>>(lstm_in, hs, Wt, bt, Wa, ba, out);
}